// round 8
// baseline (speedup 1.0000x reference)
#include <cuda_runtime.h>

#define NB 256
#define NH 500
#define NI 784
#define NO 10
#define TT 200

#define V0F  2.1165347359575993f   // f32(eta^(eta/(eta-1))/(eta-1)), eta=4
#define SIGF 0.7788007830714049f   // f32(exp(-1/4))

typedef unsigned long long u64;

// static device scratch (allowed per harness rules)
__device__ float d_ann[NB*NH];
__device__ float d_cur[TT*NB*NH];        // 102.4 MB (cur2, reused for cur3)
__device__ float d_w2[TT*NB*NH];         // 102.4 MB
__device__ float d_w3[TT*NB*NO];         // 2 MB

__device__ __forceinline__ void ffma2(u64 &acc, u64 a, u64 b) {
    asm("fma.rn.f32x2 %0, %1, %2, %0;" : "+l"(acc) : "l"(a), "l"(b));
}
__device__ __forceinline__ float2 unpack2(u64 v) {
    float2 f; asm("mov.b64 {%0,%1}, %2;" : "=f"(f.x), "=f"(f.y) : "l"(v));
    return f;
}
__device__ __forceinline__ u64 dup2(float v) {
    u64 d; asm("mov.b64 %0, {%1, %1};" : "=l"(d) : "f"(v)); return d;
}

// XLA f32 tanh (rational approx, strict unfused) + logistic expansion
__device__ __forceinline__ float xla_tanh(float x) {
    const float xc = fminf(fmaxf(x, -7.90531110763549805f), 7.90531110763549805f);
    const float x2 = __fmul_rn(xc, xc);
    float p = -2.76076847742355e-16f;
    p = __fadd_rn(__fmul_rn(p, x2),  2.00018790482477e-13f);
    p = __fadd_rn(__fmul_rn(p, x2), -8.60467152213735e-11f);
    p = __fadd_rn(__fmul_rn(p, x2),  5.12229709037114e-08f);
    p = __fadd_rn(__fmul_rn(p, x2),  1.48572235717979e-05f);
    p = __fadd_rn(__fmul_rn(p, x2),  6.37261928875436e-04f);
    p = __fadd_rn(__fmul_rn(p, x2),  4.89352455891786e-03f);
    const float num = __fmul_rn(xc, p);
    float q = 1.19825839466702e-06f;
    q = __fadd_rn(__fmul_rn(q, x2), 1.18534705686654e-04f);
    q = __fadd_rn(__fmul_rn(q, x2), 2.26843463243900e-03f);
    q = __fadd_rn(__fmul_rn(q, x2), 4.89352518554385e-03f);
    const float t = __fdiv_rn(num, q);
    return (fabsf(x) < 0.0004f) ? x : t;
}
__device__ __forceinline__ float xla_logistic(float z) {
    return __fadd_rn(0.5f, __fmul_rn(0.5f, xla_tanh(__fmul_rn(0.5f, z))));
}

// ---------------------------------------------------------------------------
// Strict GEMM v4: C[m,n] = epi(chain_k fma(A[m,k],B[n,k]) + bias[n])
// A:[M,K] row-major, B:[N,K] row-major. Tile 128m x 128n x 8k, 256 threads,
// double-buffered. A is stored DUPLICATED in smem ({a,a} u64 pairs) so the
// FFMA2 a-operand comes straight from LDS.128 with no register MOVs.
// Thread tile 8m x 8n; acc lanes pair (n, n+1). Per output: single
// accumulator, strictly k-ascending fma.rn chain (bit-exact vs reference).
// Requires: M % 128 == 0, K % 4 == 0.
// ---------------------------------------------------------------------------
__global__ void __launch_bounds__(256, 2) gemm_strict_v4(
    const float* __restrict__ A, const float* __restrict__ B,
    const float* __restrict__ bias, float* __restrict__ C,
    int M, int N, int K, int act)
{
    __shared__ float As2[2][8][264];  // [buf][k][2*m] duplicated pairs
    __shared__ float Bs [2][8][132];  // [buf][k][n]

    const int tid = threadIdx.x;
    const int tx  = tid & 15;          // n group: 8 n each
    const int ty  = tid >> 4;          // m group: 8 m each
    const int m0  = blockIdx.y * 128;
    const int j0  = blockIdx.x * 128;

    const int lr = tid >> 1;           // loader row 0..127
    const int lc = (tid & 1) * 4;      // loader k chunk {0,4}
    const bool bok = (j0 + lr) < N;
    const int nblk = (K + 7) >> 3;

    u64 acc[8][4];
#pragma unroll
    for (int i = 0; i < 8; i++)
#pragma unroll
        for (int j = 0; j < 4; j++) acc[i][j] = 0ull;

    float4 ra, rb;
    const float4 z4 = make_float4(0.f, 0.f, 0.f, 0.f);

    auto LD = [&](int blk) {
        const int kg = blk * 8 + lc;
        const bool kok = kg < K;
        ra = kok ? *reinterpret_cast<const float4*>(&A[(size_t)(m0 + lr) * K + kg]) : z4;
        rb = (kok && bok) ? *reinterpret_cast<const float4*>(&B[(size_t)(j0 + lr) * K + kg]) : z4;
    };
    auto ST = [&](int buf) {
        *reinterpret_cast<u64*>(&As2[buf][lc + 0][2 * lr]) = dup2(ra.x);
        *reinterpret_cast<u64*>(&As2[buf][lc + 1][2 * lr]) = dup2(ra.y);
        *reinterpret_cast<u64*>(&As2[buf][lc + 2][2 * lr]) = dup2(ra.z);
        *reinterpret_cast<u64*>(&As2[buf][lc + 3][2 * lr]) = dup2(ra.w);
        Bs[buf][lc + 0][lr] = rb.x;  Bs[buf][lc + 1][lr] = rb.y;
        Bs[buf][lc + 2][lr] = rb.z;  Bs[buf][lc + 3][lr] = rb.w;
    };

    LD(0); ST(0); __syncthreads();

    for (int blk = 0; blk < nblk; blk++) {
        const int buf = blk & 1;
        if (blk + 1 < nblk) LD(blk + 1);
#pragma unroll
        for (int k = 0; k < 8; k++) {
            // a-dup pairs: 4x LDS.128, broadcast within warp (2 addrs/warp)
            const ulonglong2 ad01 = *reinterpret_cast<const ulonglong2*>(&As2[buf][k][ty * 16]);
            const ulonglong2 ad23 = *reinterpret_cast<const ulonglong2*>(&As2[buf][k][ty * 16 + 4]);
            const ulonglong2 ad45 = *reinterpret_cast<const ulonglong2*>(&As2[buf][k][ty * 16 + 8]);
            const ulonglong2 ad67 = *reinterpret_cast<const ulonglong2*>(&As2[buf][k][ty * 16 + 12]);
            const u64 ad[8] = {ad01.x, ad01.y, ad23.x, ad23.y,
                               ad45.x, ad45.y, ad67.x, ad67.y};
            const ulonglong2 b01 = *reinterpret_cast<const ulonglong2*>(&Bs[buf][k][tx * 8]);
            const ulonglong2 b23 = *reinterpret_cast<const ulonglong2*>(&Bs[buf][k][tx * 8 + 4]);
            const u64 b[4] = {b01.x, b01.y, b23.x, b23.y};
#pragma unroll
            for (int mi = 0; mi < 8; mi++)
#pragma unroll
                for (int nj = 0; nj < 4; nj++) ffma2(acc[mi][nj], ad[mi], b[nj]);
        }
        if (blk + 1 < nblk) ST(buf ^ 1);
        __syncthreads();
    }

#pragma unroll
    for (int mi = 0; mi < 8; mi++) {
        const int m = m0 + ty * 8 + mi;
#pragma unroll
        for (int nj = 0; nj < 4; nj++) {
            const int n = j0 + tx * 8 + 2 * nj;
            if (n < N) {
                const float2 f = unpack2(acc[mi][nj]);
                float v0 = __fadd_rn(f.x, bias[n]);
                if (act) v0 = xla_logistic(v0);
                C[(size_t)m * N + n] = v0;
                if (n + 1 < N) {
                    float v1 = __fadd_rn(f.y, bias[n + 1]);
                    if (act) v1 = xla_logistic(v1);
                    C[(size_t)m * N + n + 1] = v1;
                }
            }
        }
    }
}

// ---- dummy: shifts ncu's captured launch slot onto K3 -----------------------
__global__ void k_dummy() {}

// ---- K2: cur2(t) for all t (IIR, no spike feedback; strict rounding) -------
__global__ void k2_cur2(const float* __restrict__ a1, const float* __restrict__ a2)
{
    const int idx = blockIdx.x * blockDim.x + threadIdx.x;
    if (idx >= NB * NH) return;
    const int j = idx % NH;
    const float c1 = a1[j], c2 = a2[j];
    const float va = __fmul_rn(V0F, d_ann[idx]);
    float p1 = 0.f, p2 = 0.f;
    for (int t = 0; t < TT; t++) {
        const float s = __fadd_rn(__fadd_rn(__fmul_rn(c1, p1), __fmul_rn(c2, p2)), va);
        d_cur[(size_t)t * NB * NH + idx] = s;
        p2 = p1; p1 = s;
    }
}

// ---- K45: fused layer-2 LIF + layer-3 IIR (strict; MLP-4 prefetch) ----------
__global__ void k45_lif2_cur3(const float* __restrict__ a1, const float* __restrict__ a2)
{
    const int idx = blockIdx.x * blockDim.x + threadIdx.x;
    if (idx >= NB * NH) return;
    const int j = idx % NH;
    const float c1 = a1[j], c2 = a2[j];
    float v = 0.f, ns = 1.f, p1 = 0.f, p2 = 0.f;
    for (int t0 = 0; t0 < TT; t0 += 4) {
        float w[4];
#pragma unroll
        for (int u = 0; u < 4; u++)
            w[u] = d_w2[(size_t)(t0 + u) * NB * NH + idx];
#pragma unroll
        for (int u = 0; u < 4; u++) {
            v = __fadd_rn(__fmul_rn(__fmul_rn(SIGF, v), ns), w[u]);
            const bool s = (__fadd_rn(v, -1.0f) > 0.f);
            ns = s ? 0.f : 1.f;
            const float inp = s ? V0F : 0.f;
            const float c = __fadd_rn(__fadd_rn(__fmul_rn(c1, p1), __fmul_rn(c2, p2)), inp);
            d_cur[(size_t)(t0 + u) * NB * NH + idx] = c;
            p2 = p1; p1 = c;
        }
    }
}

// ---- K6: w3 = cur3 @ W3^T + b3  (strict k-chain; float4 LDS) ----------------
__global__ void __launch_bounds__(640) k6_gemm3(const float* __restrict__ W3,
                                                const float* __restrict__ b3)
{
    __shared__ float W3s[NO * NH];   // 20 KB
    __shared__ float Cs[64][68];     // padded for float4 alignment
    const int tid = threadIdx.x;
    const int r0 = blockIdx.x * 64;
    for (int i = tid; i < NO * NH; i += 640) W3s[i] = W3[i];
    const int rr = tid / 10, o = tid - rr * 10;
    float acc = 0.f;
    for (int k0 = 0; k0 < NH; k0 += 64) {
        __syncthreads();
        for (int i = tid; i < 64 * 64; i += 640) {
            const int r = i >> 6, kq = i & 63, kg = k0 + kq;
            Cs[r][kq] = (kg < NH) ? d_cur[(size_t)(r0 + r) * NH + kg] : 0.f;
        }
        __syncthreads();
        const int kl = (NH - k0 < 64) ? (NH - k0) : 64;   // 64 or 52 (mult of 4)
        for (int k = 0; k < kl; k += 4) {
            const float4 c = *reinterpret_cast<const float4*>(&Cs[rr][k]);
            const float4 w = *reinterpret_cast<const float4*>(&W3s[o * NH + k0 + k]);
            acc = fmaf(c.x, w.x, acc);
            acc = fmaf(c.y, w.y, acc);
            acc = fmaf(c.z, w.z, acc);
            acc = fmaf(c.w, w.w, acc);
        }
    }
    d_w3[(size_t)(r0 + rr) * NO + o] = __fadd_rn(acc, b3[o]);
}

// ---- K7: layer-3 LIF scan -> output [B,10,T] --------------------------------
__global__ void k7_lif3(float* __restrict__ out)
{
    const int idx = blockIdx.x * blockDim.x + threadIdx.x;
    if (idx >= NB * NO) return;
    const int b = idx / NO, o = idx - b * NO;
    float v = 0.f, ns = 1.f;
    for (int t0 = 0; t0 < TT; t0 += 4) {
        float w[4];
#pragma unroll
        for (int u = 0; u < 4; u++)
            w[u] = d_w3[((size_t)(t0 + u) * NB + b) * NO + o];
#pragma unroll
        for (int u = 0; u < 4; u++) {
            v = __fadd_rn(__fmul_rn(__fmul_rn(SIGF, v), ns), w[u]);
            const bool s = (__fadd_rn(v, -1.0f) > 0.f);
            ns = s ? 0.f : 1.f;
            out[((size_t)b * NO + o) * TT + t0 + u] = s ? 1.f : 0.f;
        }
    }
}

// ---------------------------------------------------------------------------
extern "C" void kernel_launch(void* const* d_in, const int* in_sizes, int n_in,
                              void* d_out, int out_size)
{
    const float* inputs = (const float*)d_in[0];
    const float* W1     = (const float*)d_in[1];
    const float* b1     = (const float*)d_in[2];
    const float* a1_2   = (const float*)d_in[3];
    const float* a2_2   = (const float*)d_in[4];
    const float* W2     = (const float*)d_in[5];
    const float* b2     = (const float*)d_in[6];
    const float* a1_3   = (const float*)d_in[7];
    const float* a2_3   = (const float*)d_in[8];
    const float* W3     = (const float*)d_in[9];
    const float* b3     = (const float*)d_in[10];

    float* ann; cudaGetSymbolAddress((void**)&ann, d_ann);
    float* cur; cudaGetSymbolAddress((void**)&cur, d_cur);
    float* w2;  cudaGetSymbolAddress((void**)&w2,  d_w2);

    const int NRR = TT * NB;   // 51200

    // K1: ann = logistic(inputs @ W1^T + b1)     (M=256, K=784)
    gemm_strict_v4<<<dim3(4, NB / 128), 256>>>(inputs, W1, b1, ann, NB, NH, NI, 1);
    // K2: cur2 for all t
    k2_cur2<<<(NB * NH + 255) / 256, 256>>>(a1_2, a2_2);
    // dummy (positions K3 at the ncu-captured launch slot)
    k_dummy<<<1, 1>>>();
    // K3: w2 = cur2_all @ W2^T + b2              (M=51200, K=500)
    gemm_strict_v4<<<dim3(4, NRR / 128), 256>>>(cur, W2, b2, w2, NRR, NH, NH, 0);
    // K45: layer-2 LIF + layer-3 synapse IIR (fused)
    k45_lif2_cur3<<<(NB * NH + 255) / 256, 256>>>(a1_3, a2_3);
    // K6: w3 = cur3_all @ W3^T + b3
    k6_gemm3<<<NRR / 64, 640>>>(W3, b3);
    // K7: layer-3 LIF -> output
    k7_lif3<<<(NB * NO + 255) / 256, 256>>>((float*)d_out);
}

// round 9
// speedup vs baseline: 1.0917x; 1.0917x over previous
#include <cuda_runtime.h>

#define NB 256
#define NH 500
#define NI 784
#define NO 10
#define TT 200

#define V0F  2.1165347359575993f   // f32(eta^(eta/(eta-1))/(eta-1)), eta=4
#define SIGF 0.7788007830714049f   // f32(exp(-1/4))

typedef unsigned long long u64;

// static device scratch (allowed per harness rules)
__device__ float d_ann[NB*NH];
__device__ float d_cur[TT*NB*NH];        // 102.4 MB (cur2, reused for cur3)
__device__ float d_w2[TT*NB*NH];         // 102.4 MB
__device__ float d_w3[TT*NB*NO];         // 2 MB

__device__ __forceinline__ void ffma2(u64 &acc, u64 a, u64 b) {
    asm("fma.rn.f32x2 %0, %1, %2, %0;" : "+l"(acc) : "l"(a), "l"(b));
}
__device__ __forceinline__ float2 unpack2(u64 v) {
    float2 f; asm("mov.b64 {%0,%1}, %2;" : "=f"(f.x), "=f"(f.y) : "l"(v));
    return f;
}
__device__ __forceinline__ u64 dup2(float v) {
    u64 d; asm("mov.b64 %0, {%1, %1};" : "=l"(d) : "f"(v)); return d;
}

// XLA f32 tanh (rational approx, strict unfused) + logistic expansion
__device__ __forceinline__ float xla_tanh(float x) {
    const float xc = fminf(fmaxf(x, -7.90531110763549805f), 7.90531110763549805f);
    const float x2 = __fmul_rn(xc, xc);
    float p = -2.76076847742355e-16f;
    p = __fadd_rn(__fmul_rn(p, x2),  2.00018790482477e-13f);
    p = __fadd_rn(__fmul_rn(p, x2), -8.60467152213735e-11f);
    p = __fadd_rn(__fmul_rn(p, x2),  5.12229709037114e-08f);
    p = __fadd_rn(__fmul_rn(p, x2),  1.48572235717979e-05f);
    p = __fadd_rn(__fmul_rn(p, x2),  6.37261928875436e-04f);
    p = __fadd_rn(__fmul_rn(p, x2),  4.89352455891786e-03f);
    const float num = __fmul_rn(xc, p);
    float q = 1.19825839466702e-06f;
    q = __fadd_rn(__fmul_rn(q, x2), 1.18534705686654e-04f);
    q = __fadd_rn(__fmul_rn(q, x2), 2.26843463243900e-03f);
    q = __fadd_rn(__fmul_rn(q, x2), 4.89352518554385e-03f);
    const float t = __fdiv_rn(num, q);
    return (fabsf(x) < 0.0004f) ? x : t;
}
__device__ __forceinline__ float xla_logistic(float z) {
    return __fadd_rn(0.5f, __fmul_rn(0.5f, xla_tanh(__fmul_rn(0.5f, z))));
}

// ---------------------------------------------------------------------------
// Strict GEMM v5: C[m,n] = epi(chain_k fma(A[m,k],B[n,k]) + bias[n])
// Tile 256m x 64n x 8k, 256 threads, double-buffered.
// Warp shape 8tx x 4ty; thread tile 8m x 8n, acc lanes pair (n, n+1).
// A stored DUPLICATED in smem, 20-float-strided chunks (bank-conflict-free);
// B in 12-float-strided chunks. Every compute LDS.128 = 1 wavefront.
// Per output: single accumulator, strictly k-ascending fma.rn chain.
// Requires: M % 256 == 0, K % 4 == 0.
// ---------------------------------------------------------------------------
__global__ void __launch_bounds__(256, 2) gemm_strict_v5(
    const float* __restrict__ A, const float* __restrict__ B,
    const float* __restrict__ bias, float* __restrict__ C,
    int M, int N, int K, int act)
{
    __shared__ float As2[2][8][644];  // 32 chunks x (16 dup + 4 pad)
    __shared__ float Bs [2][8][100];  // 8 chunks x (8 + 4 pad)

    const int tid = threadIdx.x;
    const int tx  = tid & 7;           // n group: 8 n each
    const int ty  = tid >> 3;          // m group: 8 m each (0..31)
    const int m0  = blockIdx.y * 256;
    const int j0  = blockIdx.x * 64;

    // A loader: row m0+tid, 8 k values (2x float4)
    // B loader: row j0+(tid>>2), 2 k values at (tid&3)*2 (float2)
    const int bLr = tid >> 2;
    const int bLc = (tid & 3) * 2;
    const bool bok = (j0 + bLr) < N;
    const int aSoff = (tid >> 3) * 20 + (tid & 7) * 2;   // dup-pair float offset
    const int bSoff = (bLr >> 3) * 12 + (bLr & 7);
    const int nblk = (K + 7) >> 3;

    u64 acc[8][4];
#pragma unroll
    for (int i = 0; i < 8; i++)
#pragma unroll
        for (int j = 0; j < 4; j++) acc[i][j] = 0ull;

    float4 ra0, ra1; float2 rb;
    const float4 z4 = make_float4(0.f, 0.f, 0.f, 0.f);

    auto LD = [&](int blk) {
        const int kg = blk * 8;
        ra0 = (kg < K)     ? *reinterpret_cast<const float4*>(&A[(size_t)(m0 + tid) * K + kg]) : z4;
        ra1 = (kg + 4 < K) ? *reinterpret_cast<const float4*>(&A[(size_t)(m0 + tid) * K + kg + 4]) : z4;
        const int kgb = kg + bLc;
        rb = (kgb < K && bok) ? *reinterpret_cast<const float2*>(&B[(size_t)(j0 + bLr) * K + kgb])
                              : make_float2(0.f, 0.f);
    };
    auto ST = [&](int buf) {
        *reinterpret_cast<u64*>(&As2[buf][0][aSoff]) = dup2(ra0.x);
        *reinterpret_cast<u64*>(&As2[buf][1][aSoff]) = dup2(ra0.y);
        *reinterpret_cast<u64*>(&As2[buf][2][aSoff]) = dup2(ra0.z);
        *reinterpret_cast<u64*>(&As2[buf][3][aSoff]) = dup2(ra0.w);
        *reinterpret_cast<u64*>(&As2[buf][4][aSoff]) = dup2(ra1.x);
        *reinterpret_cast<u64*>(&As2[buf][5][aSoff]) = dup2(ra1.y);
        *reinterpret_cast<u64*>(&As2[buf][6][aSoff]) = dup2(ra1.z);
        *reinterpret_cast<u64*>(&As2[buf][7][aSoff]) = dup2(ra1.w);
        Bs[buf][bLc + 0][bSoff] = rb.x;
        Bs[buf][bLc + 1][bSoff] = rb.y;
    };

    LD(0); ST(0); __syncthreads();

    for (int blk = 0; blk < nblk; blk++) {
        const int buf = blk & 1;
        if (blk + 1 < nblk) LD(blk + 1);
#pragma unroll
        for (int k = 0; k < 8; k++) {
            const ulonglong2 ad01 = *reinterpret_cast<const ulonglong2*>(&As2[buf][k][ty * 20]);
            const ulonglong2 ad23 = *reinterpret_cast<const ulonglong2*>(&As2[buf][k][ty * 20 + 4]);
            const ulonglong2 ad45 = *reinterpret_cast<const ulonglong2*>(&As2[buf][k][ty * 20 + 8]);
            const ulonglong2 ad67 = *reinterpret_cast<const ulonglong2*>(&As2[buf][k][ty * 20 + 12]);
            const u64 ad[8] = {ad01.x, ad01.y, ad23.x, ad23.y,
                               ad45.x, ad45.y, ad67.x, ad67.y};
            const ulonglong2 b01 = *reinterpret_cast<const ulonglong2*>(&Bs[buf][k][tx * 12]);
            const ulonglong2 b23 = *reinterpret_cast<const ulonglong2*>(&Bs[buf][k][tx * 12 + 4]);
            const u64 b[4] = {b01.x, b01.y, b23.x, b23.y};
#pragma unroll
            for (int mi = 0; mi < 8; mi++)
#pragma unroll
                for (int nj = 0; nj < 4; nj++) ffma2(acc[mi][nj], ad[mi], b[nj]);
        }
        if (blk + 1 < nblk) ST(buf ^ 1);
        __syncthreads();
    }

#pragma unroll
    for (int mi = 0; mi < 8; mi++) {
        const int m = m0 + ty * 8 + mi;
#pragma unroll
        for (int nj = 0; nj < 4; nj++) {
            const int n = j0 + tx * 8 + 2 * nj;
            if (n < N) {
                const float2 f = unpack2(acc[mi][nj]);
                float v0 = __fadd_rn(f.x, bias[n]);
                if (act) v0 = xla_logistic(v0);
                C[(size_t)m * N + n] = v0;
                if (n + 1 < N) {
                    float v1 = __fadd_rn(f.y, bias[n + 1]);
                    if (act) v1 = xla_logistic(v1);
                    C[(size_t)m * N + n + 1] = v1;
                }
            }
        }
    }
}

// ---------------------------------------------------------------------------
// Strict small GEMM (for K1): tile 64m x 64n x 8k, 256 threads, 4m x 4n/thread.
// Same strict chain semantics. Requires M % 64 == 0, K % 4 == 0.
// ---------------------------------------------------------------------------
__global__ void __launch_bounds__(256) gemm_strict_small(
    const float* __restrict__ A, const float* __restrict__ B,
    const float* __restrict__ bias, float* __restrict__ C,
    int M, int N, int K, int act)
{
    __shared__ float As2[2][8][132];  // 64 m dup = 128 floats (+pad)
    __shared__ float Bs [2][8][68];

    const int tid = threadIdx.x;
    const int tx  = tid & 15;          // n group: 4 n each
    const int ty  = tid >> 4;          // m group: 4 m each
    const int m0  = blockIdx.y * 64;
    const int j0  = blockIdx.x * 64;

    const int lr = tid >> 2;           // 0..63
    const int lc = (tid & 3) * 2;      // {0,2,4,6}
    const bool bok = (j0 + lr) < N;
    const int nblk = (K + 7) >> 3;

    u64 acc[4][2];
#pragma unroll
    for (int i = 0; i < 4; i++) { acc[i][0] = 0ull; acc[i][1] = 0ull; }

    float2 ra, rb;

    auto LD = [&](int blk) {
        const int kg = blk * 8 + lc;
        const bool kok = kg < K;
        ra = kok ? *reinterpret_cast<const float2*>(&A[(size_t)(m0 + lr) * K + kg])
                 : make_float2(0.f, 0.f);
        rb = (kok && bok) ? *reinterpret_cast<const float2*>(&B[(size_t)(j0 + lr) * K + kg])
                          : make_float2(0.f, 0.f);
    };
    auto ST = [&](int buf) {
        *reinterpret_cast<u64*>(&As2[buf][lc + 0][2 * lr]) = dup2(ra.x);
        *reinterpret_cast<u64*>(&As2[buf][lc + 1][2 * lr]) = dup2(ra.y);
        Bs[buf][lc + 0][lr] = rb.x;
        Bs[buf][lc + 1][lr] = rb.y;
    };

    LD(0); ST(0); __syncthreads();

    for (int blk = 0; blk < nblk; blk++) {
        const int buf = blk & 1;
        if (blk + 1 < nblk) LD(blk + 1);
#pragma unroll
        for (int k = 0; k < 8; k++) {
            const ulonglong2 ad01 = *reinterpret_cast<const ulonglong2*>(&As2[buf][k][ty * 8]);
            const ulonglong2 ad23 = *reinterpret_cast<const ulonglong2*>(&As2[buf][k][ty * 8 + 4]);
            const u64 ad[4] = {ad01.x, ad01.y, ad23.x, ad23.y};
            const ulonglong2 bv = *reinterpret_cast<const ulonglong2*>(&Bs[buf][k][tx * 4]);
            const u64 b[2] = {bv.x, bv.y};
#pragma unroll
            for (int mi = 0; mi < 4; mi++) {
                ffma2(acc[mi][0], ad[mi], b[0]);
                ffma2(acc[mi][1], ad[mi], b[1]);
            }
        }
        if (blk + 1 < nblk) ST(buf ^ 1);
        __syncthreads();
    }

#pragma unroll
    for (int mi = 0; mi < 4; mi++) {
        const int m = m0 + ty * 4 + mi;
#pragma unroll
        for (int nj = 0; nj < 2; nj++) {
            const int n = j0 + tx * 4 + 2 * nj;
            if (n < N) {
                const float2 f = unpack2(acc[mi][nj]);
                float v0 = __fadd_rn(f.x, bias[n]);
                if (act) v0 = xla_logistic(v0);
                C[(size_t)m * N + n] = v0;
                if (n + 1 < N) {
                    float v1 = __fadd_rn(f.y, bias[n + 1]);
                    if (act) v1 = xla_logistic(v1);
                    C[(size_t)m * N + n + 1] = v1;
                }
            }
        }
    }
}

// ---- dummy: keeps K3 at the ncu-captured launch slot ------------------------
__global__ void k_dummy() {}

// ---- K2: cur2(t) for all t (IIR, no spike feedback; strict rounding) -------
__global__ void k2_cur2(const float* __restrict__ a1, const float* __restrict__ a2)
{
    const int idx = blockIdx.x * blockDim.x + threadIdx.x;
    if (idx >= NB * NH) return;
    const int j = idx % NH;
    const float c1 = a1[j], c2 = a2[j];
    const float va = __fmul_rn(V0F, d_ann[idx]);
    float p1 = 0.f, p2 = 0.f;
    for (int t = 0; t < TT; t++) {
        const float s = __fadd_rn(__fadd_rn(__fmul_rn(c1, p1), __fmul_rn(c2, p2)), va);
        d_cur[(size_t)t * NB * NH + idx] = s;
        p2 = p1; p1 = s;
    }
}

// ---- K45: fused layer-2 LIF + layer-3 IIR (strict; MLP-4 prefetch) ----------
__global__ void k45_lif2_cur3(const float* __restrict__ a1, const float* __restrict__ a2)
{
    const int idx = blockIdx.x * blockDim.x + threadIdx.x;
    if (idx >= NB * NH) return;
    const int j = idx % NH;
    const float c1 = a1[j], c2 = a2[j];
    float v = 0.f, ns = 1.f, p1 = 0.f, p2 = 0.f;
    for (int t0 = 0; t0 < TT; t0 += 4) {
        float w[4];
#pragma unroll
        for (int u = 0; u < 4; u++)
            w[u] = d_w2[(size_t)(t0 + u) * NB * NH + idx];
#pragma unroll
        for (int u = 0; u < 4; u++) {
            v = __fadd_rn(__fmul_rn(__fmul_rn(SIGF, v), ns), w[u]);
            const bool s = (__fadd_rn(v, -1.0f) > 0.f);
            ns = s ? 0.f : 1.f;
            const float inp = s ? V0F : 0.f;
            const float c = __fadd_rn(__fadd_rn(__fmul_rn(c1, p1), __fmul_rn(c2, p2)), inp);
            d_cur[(size_t)(t0 + u) * NB * NH + idx] = c;
            p2 = p1; p1 = c;
        }
    }
}

// ---- K6: w3 = cur3 @ W3^T + b3  (strict k-chain; float4 LDS) ----------------
__global__ void __launch_bounds__(640) k6_gemm3(const float* __restrict__ W3,
                                                const float* __restrict__ b3)
{
    __shared__ float W3s[NO * NH];   // 20 KB
    __shared__ float Cs[64][68];     // padded for float4 alignment
    const int tid = threadIdx.x;
    const int r0 = blockIdx.x * 64;
    for (int i = tid; i < NO * NH; i += 640) W3s[i] = W3[i];
    const int rr = tid / 10, o = tid - rr * 10;
    float acc = 0.f;
    for (int k0 = 0; k0 < NH; k0 += 64) {
        __syncthreads();
        for (int i = tid; i < 64 * 64; i += 640) {
            const int r = i >> 6, kq = i & 63, kg = k0 + kq;
            Cs[r][kq] = (kg < NH) ? d_cur[(size_t)(r0 + r) * NH + kg] : 0.f;
        }
        __syncthreads();
        const int kl = (NH - k0 < 64) ? (NH - k0) : 64;   // 64 or 52 (mult of 4)
        for (int k = 0; k < kl; k += 4) {
            const float4 c = *reinterpret_cast<const float4*>(&Cs[rr][k]);
            const float4 w = *reinterpret_cast<const float4*>(&W3s[o * NH + k0 + k]);
            acc = fmaf(c.x, w.x, acc);
            acc = fmaf(c.y, w.y, acc);
            acc = fmaf(c.z, w.z, acc);
            acc = fmaf(c.w, w.w, acc);
        }
    }
    d_w3[(size_t)(r0 + rr) * NO + o] = __fadd_rn(acc, b3[o]);
}

// ---- K7: layer-3 LIF scan -> output [B,10,T] --------------------------------
__global__ void k7_lif3(float* __restrict__ out)
{
    const int idx = blockIdx.x * blockDim.x + threadIdx.x;
    if (idx >= NB * NO) return;
    const int b = idx / NO, o = idx - b * NO;
    float v = 0.f, ns = 1.f;
    for (int t0 = 0; t0 < TT; t0 += 4) {
        float w[4];
#pragma unroll
        for (int u = 0; u < 4; u++)
            w[u] = d_w3[((size_t)(t0 + u) * NB + b) * NO + o];
#pragma unroll
        for (int u = 0; u < 4; u++) {
            v = __fadd_rn(__fmul_rn(__fmul_rn(SIGF, v), ns), w[u]);
            const bool s = (__fadd_rn(v, -1.0f) > 0.f);
            ns = s ? 0.f : 1.f;
            out[((size_t)b * NO + o) * TT + t0 + u] = s ? 1.f : 0.f;
        }
    }
}

// ---------------------------------------------------------------------------
extern "C" void kernel_launch(void* const* d_in, const int* in_sizes, int n_in,
                              void* d_out, int out_size)
{
    const float* inputs = (const float*)d_in[0];
    const float* W1     = (const float*)d_in[1];
    const float* b1     = (const float*)d_in[2];
    const float* a1_2   = (const float*)d_in[3];
    const float* a2_2   = (const float*)d_in[4];
    const float* W2     = (const float*)d_in[5];
    const float* b2     = (const float*)d_in[6];
    const float* a1_3   = (const float*)d_in[7];
    const float* a2_3   = (const float*)d_in[8];
    const float* W3     = (const float*)d_in[9];
    const float* b3     = (const float*)d_in[10];

    float* ann; cudaGetSymbolAddress((void**)&ann, d_ann);
    float* cur; cudaGetSymbolAddress((void**)&cur, d_cur);
    float* w2;  cudaGetSymbolAddress((void**)&w2,  d_w2);

    const int NRR = TT * NB;   // 51200

    // K1: ann = logistic(inputs @ W1^T + b1)     (M=256, K=784) — 32 CTAs
    gemm_strict_small<<<dim3(8, NB / 64), 256>>>(inputs, W1, b1, ann, NB, NH, NI, 1);
    // K2: cur2 for all t
    k2_cur2<<<(NB * NH + 255) / 256, 256>>>(a1_2, a2_2);
    // dummy (keeps K3 at the ncu-captured launch slot)
    k_dummy<<<1, 1>>>();
    // K3: w2 = cur2_all @ W2^T + b2              (M=51200, K=500)
    gemm_strict_v5<<<dim3(8, NRR / 256), 256>>>(cur, W2, b2, w2, NRR, NH, NH, 0);
    // K45: layer-2 LIF + layer-3 synapse IIR (fused)
    k45_lif2_cur3<<<(NB * NH + 255) / 256, 256>>>(a1_3, a2_3);
    // K6: w3 = cur3_all @ W3^T + b3
    k6_gemm3<<<NRR / 64, 640>>>(W3, b3);
    // K7: layer-3 LIF -> output
    k7_lif3<<<(NB * NO + 255) / 256, 256>>>((float*)d_out);
}